// round 14
// baseline (speedup 1.0000x reference)
#include <cuda_runtime.h>
#include <cuda_fp16.h>
#include <math.h>

// ---------------- problem constants ----------------
#define NMAX      50000
#define EMAX      800000
#define CH        128
#define NGRAPHS   64
#define BN_EPS    1e-5f

// ---------------- scratch (device globals) ----------------
__device__ __half g_hw[NMAX * CH];    // GEMM output, rows pre-scaled by dinv (fp16)
__device__ float g_actA[NMAX * CH];
__device__ float g_actB[NMAX * CH];
__device__ float g_dinv[NMAX];
__device__ int   g_indeg[NMAX];
__device__ int   g_rowstart[NMAX + 1];
__device__ int   g_fill[NMAX];
__device__ int   g_edges[EMAX];
__device__ int   g_blocksum[64];
__device__ int   g_blockoff[64];
__device__ float g_bnsum[3 * 2 * CH];
__device__ float g_pool[NGRAPHS * CH + NGRAPHS];
__device__ float g_y1[NGRAPHS * CH];
__device__ float g_y2[NGRAPHS * CH];

// ---------------- helpers ----------------
__device__ __forceinline__ float gelu_exact(float x) {
    return 0.5f * x * (1.0f + erff(x * 0.70710678118654752440f));
}

// tanh-form gelu using HW MUFU.TANH (sm_90+)
__device__ __forceinline__ float gelu_fast(float x) {
    float u = x * (0.7978845608028654f + 0.035677408136300125f * x * x);
    float t;
    asm("tanh.approx.f32 %0, %1;" : "=f"(t) : "f"(u));
    return 0.5f * x * (1.0f + t);
}

__device__ __forceinline__ unsigned h2u(__half2 h) { return *reinterpret_cast<unsigned*>(&h); }

__device__ __forceinline__ void ldsm_x4(unsigned r[4], const void* p) {
    unsigned addr = (unsigned)__cvta_generic_to_shared(p);
    asm volatile("ldmatrix.sync.aligned.m8n8.x4.shared.b16 {%0,%1,%2,%3}, [%4];"
                 : "=r"(r[0]), "=r"(r[1]), "=r"(r[2]), "=r"(r[3]) : "r"(addr));
}
__device__ __forceinline__ void ldsm_x4_t(unsigned r[4], const void* p) {
    unsigned addr = (unsigned)__cvta_generic_to_shared(p);
    asm volatile("ldmatrix.sync.aligned.m8n8.x4.trans.shared.b16 {%0,%1,%2,%3}, [%4];"
                 : "=r"(r[0]), "=r"(r[1]), "=r"(r[2]), "=r"(r[3]) : "r"(addr));
}
__device__ __forceinline__ void mma16816(float c[4], const unsigned a[4],
                                         unsigned b0, unsigned b1) {
    asm volatile(
        "mma.sync.aligned.m16n8k16.row.col.f32.f16.f16.f32 "
        "{%0,%1,%2,%3}, {%4,%5,%6,%7}, {%8,%9}, {%0,%1,%2,%3};"
        : "+f"(c[0]), "+f"(c[1]), "+f"(c[2]), "+f"(c[3])
        : "r"(a[0]), "r"(a[1]), "r"(a[2]), "r"(a[3]), "r"(b0), "r"(b1));
}

// ---------------- init ----------------
__global__ void k_init(int* __restrict__ indeg, float* __restrict__ bnsum,
                       float* __restrict__ pool, int N) {
    int i = blockIdx.x * blockDim.x + threadIdx.x;
    int st = gridDim.x * blockDim.x;
    for (int j = i; j < N; j += st) indeg[j] = 0;
    for (int j = i; j < 3 * 2 * CH; j += st) bnsum[j] = 0.f;
    for (int j = i; j < NGRAPHS * CH + NGRAPHS; j += st) pool[j] = 0.f;
}

// ---------------- degree / CSR build (MLP-4 batched atomics) ----------------
__global__ void k_count(const int* __restrict__ dst, int* __restrict__ indeg, int E) {
    int i0 = blockIdx.x * (blockDim.x * 4) + threadIdx.x;
    int d[4];
    #pragma unroll
    for (int k = 0; k < 4; k++) {
        int i = i0 + k * 256;
        if (i < E) d[k] = __ldg(&dst[i]);
    }
    #pragma unroll
    for (int k = 0; k < 4; k++) {
        int i = i0 + k * 256;
        if (i < E) atomicAdd(&indeg[d[k]], 1);
    }
}

__global__ void k_scan_blk(const int* __restrict__ indeg, int* __restrict__ scanned,
                           int* __restrict__ blocksum, float* __restrict__ dinv, int N) {
    __shared__ int wsum[32];
    int tid = threadIdx.x, lane = tid & 31, wid = tid >> 5;
    int idx = blockIdx.x * 1024 + tid;
    int v = (idx < N) ? indeg[idx] : 0;
    if (idx < N) dinv[idx] = rsqrtf((float)(v + 1));
    int x = v;
    #pragma unroll
    for (int off = 1; off < 32; off <<= 1) {
        int y = __shfl_up_sync(0xffffffffu, x, off);
        if (lane >= off) x += y;
    }
    if (lane == 31) wsum[wid] = x;
    __syncthreads();
    if (wid == 0) {
        int w = wsum[lane];
        #pragma unroll
        for (int off = 1; off < 32; off <<= 1) {
            int y = __shfl_up_sync(0xffffffffu, w, off);
            if (lane >= off) w += y;
        }
        wsum[lane] = w;
    }
    __syncthreads();
    int excl = x - v + (wid ? wsum[wid - 1] : 0);
    if (idx < N) scanned[idx] = excl;
    if (tid == 1023) blocksum[blockIdx.x] = excl + v;
}

__global__ void k_scan_top(const int* __restrict__ blocksum, int* __restrict__ blockoff,
                           int* __restrict__ rowstart, int B, int N) {
    int lane = threadIdx.x;
    int run = 0;
    for (int base = 0; base < B; base += 32) {
        int v = (base + lane < B) ? blocksum[base + lane] : 0;
        int x = v;
        #pragma unroll
        for (int off = 1; off < 32; off <<= 1) {
            int y = __shfl_up_sync(0xffffffffu, x, off);
            if (lane >= off) x += y;
        }
        if (base + lane < B) blockoff[base + lane] = x - v + run;
        run += __shfl_sync(0xffffffffu, x, 31);
    }
    if (lane == 0) rowstart[N] = run;
}

__global__ void k_scan_add(int* __restrict__ rowstart, const int* __restrict__ blockoff,
                           int* __restrict__ fill, int N) {
    int idx = blockIdx.x * blockDim.x + threadIdx.x;
    if (idx < N) {
        int v = rowstart[idx] + blockoff[idx >> 10];
        rowstart[idx] = v;
        fill[idx] = v;
    }
}

__global__ void k_fillcsr(const int* __restrict__ src, const int* __restrict__ dst,
                          int* __restrict__ fill, int* __restrict__ edges, int E) {
    int i0 = blockIdx.x * (blockDim.x * 4) + threadIdx.x;
    int s[4], d[4];
    #pragma unroll
    for (int k = 0; k < 4; k++) {
        int i = i0 + k * 256;
        if (i < E) { s[k] = __ldg(&src[i]); d[k] = __ldg(&dst[i]); }
    }
    int pos[4];
    #pragma unroll
    for (int k = 0; k < 4; k++) {
        int i = i0 + k * 256;
        if (i < E) pos[k] = atomicAdd(&fill[d[k]], 1);
    }
    #pragma unroll
    for (int k = 0; k < 4; k++) {
        int i = i0 + k * 256;
        if (i < E) edges[pos[k]] = s[k];
    }
}

// ---------------- tensor-core GEMM with optional fused BN+gelu on A ----------------
#define BM 128

__global__ void __launch_bounds__(256, 2)
k_gemm(const float* __restrict__ A, const float* __restrict__ W,
       const float* __restrict__ dinv,
       const float* __restrict__ bnsum, const float* __restrict__ gamma,
       const float* __restrict__ beta, float invN,
       __half* __restrict__ out, int N) {
    __shared__ __half sA[128][72];
    __shared__ __half sB[64][136];
    __shared__ float scl[CH], shf[CH];

    int tid = threadIdx.x;
    int lane = tid & 31, wid = tid >> 5;
    int warpM = wid >> 1, warpN = wid & 1;
    int rowBase = blockIdx.x * BM;

    if (bnsum) {
        if (tid < CH) {
            float mean = bnsum[tid] * invN;
            float var = bnsum[CH + tid] * invN - mean * mean;
            float s = gamma[tid] * rsqrtf(var + BN_EPS);
            scl[tid] = s;
            shf[tid] = beta[tid] - mean * s;
        }
        __syncthreads();
    }

    float acc[2][8][4];
    #pragma unroll
    for (int mi = 0; mi < 2; mi++)
        #pragma unroll
        for (int ni = 0; ni < 8; ni++)
            #pragma unroll
            for (int j = 0; j < 4; j++) acc[mi][ni][j] = 0.f;

    for (int kt = 0; kt < CH; kt += 64) {
        #pragma unroll
        for (int i = 0; i < 8; i++) {
            int p = tid + i * 256;
            int r = p >> 4, c4 = p & 15;
            float4 v = make_float4(0.f, 0.f, 0.f, 0.f);
            int grow = rowBase + r;
            if (grow < N) v = *(const float4*)&A[grow * CH + kt + c4 * 4];
            if (bnsum) {
                int c = kt + c4 * 4;
                v.x = gelu_fast(v.x * scl[c + 0] + shf[c + 0]);
                v.y = gelu_fast(v.y * scl[c + 1] + shf[c + 1]);
                v.z = gelu_fast(v.z * scl[c + 2] + shf[c + 2]);
                v.w = gelu_fast(v.w * scl[c + 3] + shf[c + 3]);
            }
            __half2 h0 = __floats2half2_rn(v.x, v.y);
            __half2 h1 = __floats2half2_rn(v.z, v.w);
            *(uint2*)&sA[r][c4 * 4] = make_uint2(h2u(h0), h2u(h1));
        }
        #pragma unroll
        for (int i = 0; i < 8; i++) {
            int p = tid + i * 256;
            int r = p >> 5, c4 = p & 31;
            float4 v = *(const float4*)&W[(kt + r) * CH + c4 * 4];
            __half2 h0 = __floats2half2_rn(v.x, v.y);
            __half2 h1 = __floats2half2_rn(v.z, v.w);
            *(uint2*)&sB[r][c4 * 4] = make_uint2(h2u(h0), h2u(h1));
        }
        __syncthreads();

        #pragma unroll
        for (int ks = 0; ks < 64; ks += 16) {
            unsigned af[2][4];
            #pragma unroll
            for (int mi = 0; mi < 2; mi++) {
                int r = warpM * 32 + mi * 16 + (lane & 15);
                int c = ks + (lane >> 4) * 8;
                ldsm_x4(af[mi], &sA[r][c]);
            }
            unsigned bf[4][4];
            #pragma unroll
            for (int nj = 0; nj < 4; nj++) {
                int r = ks + (lane & 15);
                int c = warpN * 64 + nj * 16 + (lane >> 4) * 8;
                ldsm_x4_t(bf[nj], &sB[r][c]);
            }
            #pragma unroll
            for (int mi = 0; mi < 2; mi++)
                #pragma unroll
                for (int ni = 0; ni < 8; ni++)
                    mma16816(acc[mi][ni], af[mi],
                             bf[ni >> 1][(ni & 1) * 2], bf[ni >> 1][(ni & 1) * 2 + 1]);
        }
        __syncthreads();
    }

    #pragma unroll
    for (int mi = 0; mi < 2; mi++) {
        int r0 = rowBase + warpM * 32 + mi * 16 + (lane >> 2);
        int r1 = r0 + 8;
        float d0 = (r0 < N) ? dinv[r0] : 0.f;
        float d1 = (r1 < N) ? dinv[r1] : 0.f;
        #pragma unroll
        for (int ni = 0; ni < 8; ni++) {
            int col = warpN * 64 + ni * 8 + (lane & 3) * 2;
            if (r0 < N) {
                __half2 h = __floats2half2_rn(acc[mi][ni][0] * d0, acc[mi][ni][1] * d0);
                *(__half2*)&out[r0 * CH + col] = h;
            }
            if (r1 < N) {
                __half2 h = __floats2half2_rn(acc[mi][ni][2] * d1, acc[mi][ni][3] * d1);
                *(__half2*)&out[r1 * CH + col] = h;
            }
        }
    }
}

// ---------------- aggregation: cascaded-unroll gather (MLP 16/8/4) ----------------
__device__ __forceinline__ void acc_h4(float4& a, uint2 v) {
    __half2 h0 = *reinterpret_cast<__half2*>(&v.x);
    __half2 h1 = *reinterpret_cast<__half2*>(&v.y);
    float2 f0 = __half22float2(h0);
    float2 f1 = __half22float2(h1);
    a.x += f0.x; a.y += f0.y; a.z += f1.x; a.w += f1.y;
}

__global__ void k_agg(const __half* __restrict__ hws, const int* __restrict__ edges,
                      const int* __restrict__ rowstart, const float* __restrict__ dinv,
                      const float* __restrict__ bias, float* __restrict__ outf,
                      float* __restrict__ stats, int N) {
    __shared__ float sh[8][CH];
    int wId = threadIdx.x >> 5;
    int lane = threadIdx.x & 31;
    int node = blockIdx.x * 8 + wId;
    bool valid = node < N;

    const uint2* base = (const uint2*)hws;
    float4 acc = make_float4(0.f, 0.f, 0.f, 0.f);
    float4 acc2 = make_float4(0.f, 0.f, 0.f, 0.f);
    int s = 0, e = 0;
    float d = 0.f;
    if (valid) {
        acc_h4(acc, base[node * 32 + lane]);   // self loop (pre-scaled by dinv)
        s = rowstart[node]; e = rowstart[node + 1];
        d = dinv[node];
    }
    int i = s;
    // MLP-16 main batches
    for (; i + 15 < e; i += 16) {
        int idx[16];
        #pragma unroll
        for (int j = 0; j < 16; j++) idx[j] = __ldg(&edges[i + j]);
        uint2 v[16];
        #pragma unroll
        for (int j = 0; j < 16; j++) v[j] = base[idx[j] * 32 + lane];
        #pragma unroll
        for (int j = 0; j < 16; j += 2) { acc_h4(acc, v[j]); acc_h4(acc2, v[j + 1]); }
    }
    // MLP-8 step
    if (i + 7 < e) {
        int idx[8];
        #pragma unroll
        for (int j = 0; j < 8; j++) idx[j] = __ldg(&edges[i + j]);
        uint2 v[8];
        #pragma unroll
        for (int j = 0; j < 8; j++) v[j] = base[idx[j] * 32 + lane];
        #pragma unroll
        for (int j = 0; j < 8; j += 2) { acc_h4(acc, v[j]); acc_h4(acc2, v[j + 1]); }
        i += 8;
    }
    // MLP-4 step
    if (i + 3 < e) {
        int idx[4];
        #pragma unroll
        for (int j = 0; j < 4; j++) idx[j] = __ldg(&edges[i + j]);
        uint2 v[4];
        #pragma unroll
        for (int j = 0; j < 4; j++) v[j] = base[idx[j] * 32 + lane];
        acc_h4(acc, v[0]); acc_h4(acc2, v[1]); acc_h4(acc, v[2]); acc_h4(acc2, v[3]);
        i += 4;
    }
    // singles (<=3 left): load all first, then accumulate
    {
        int rem = e - i;
        if (rem > 0) {
            int idx[3];
            for (int j = 0; j < rem; j++) idx[j] = __ldg(&edges[i + j]);
            uint2 v[3];
            for (int j = 0; j < rem; j++) v[j] = base[idx[j] * 32 + lane];
            for (int j = 0; j < rem; j++) acc_h4(acc, v[j]);
        }
    }
    acc.x += acc2.x; acc.y += acc2.y; acc.z += acc2.z; acc.w += acc2.w;

    float4 o = make_float4(0.f, 0.f, 0.f, 0.f);
    if (valid) {
        float4 bb = ((const float4*)bias)[lane];
        o.x = acc.x * d + bb.x; o.y = acc.y * d + bb.y;
        o.z = acc.z * d + bb.z; o.w = acc.w * d + bb.w;
        ((float4*)outf)[node * 32 + lane] = o;
    }
    if (stats) {
        *(float4*)&sh[wId][lane * 4] = o;
        __syncthreads();
        int t = threadIdx.x;
        int c = t & 127;
        bool sq = t >= 128;
        float a2 = 0.f;
        #pragma unroll
        for (int w = 0; w < 8; w++) {
            float v = sh[w][c];
            a2 += sq ? v * v : v;
        }
        atomicAdd(&stats[sq ? CH + c : c], a2);
    }
}

// ---------------- pooling ----------------
__global__ void k_pool(const float* __restrict__ h, const int* __restrict__ batch,
                       float* __restrict__ psum, float* __restrict__ pcnt, int N) {
    __shared__ float sh[NGRAPHS * CH];
    __shared__ float shc[NGRAPHS];
    int tid = threadIdx.x;
    for (int i = tid; i < NGRAPHS * CH; i += 256) sh[i] = 0.f;
    if (tid < NGRAPHS) shc[tid] = 0.f;
    __syncthreads();
    int rpb = (N + gridDim.x - 1) / gridDim.x;
    int r0 = blockIdx.x * rpb;
    int r1 = min(r0 + rpb, N);
    int col = tid & 127;
    for (int r = r0 + (tid >> 7); r < r1; r += 2) {
        int g = batch[r];
        atomicAdd(&sh[g * CH + col], h[r * CH + col]);
        if (col == 0) atomicAdd(&shc[g], 1.0f);
    }
    __syncthreads();
    for (int i = tid; i < NGRAPHS * CH; i += 256)
        if (sh[i] != 0.f) atomicAdd(&psum[i], sh[i]);
    if (tid < NGRAPHS && shc[tid] != 0.f) atomicAdd(&pcnt[tid], shc[tid]);
}

// ---------------- head ----------------
__global__ void k_head1(const float* __restrict__ psum, const float* __restrict__ pcnt,
                        const float* __restrict__ W, const float* __restrict__ b,
                        float* __restrict__ y) {
    __shared__ float row[CH];
    int g = blockIdx.x, t = threadIdx.x;
    float cnt = fmaxf(pcnt[g], 1.0f);
    row[t] = psum[g * CH + t] / cnt;
    __syncthreads();
    float acc = b[t];
    #pragma unroll 8
    for (int k = 0; k < CH; k++) acc += row[k] * W[k * CH + t];
    y[g * CH + t] = gelu_exact(acc);
}

__global__ void k_head2(const float* __restrict__ x, const float* __restrict__ W,
                        const float* __restrict__ b, float* __restrict__ y) {
    __shared__ float row[CH];
    int g = blockIdx.x, t = threadIdx.x;
    row[t] = x[g * CH + t];
    __syncthreads();
    float acc = b[t];
    #pragma unroll 8
    for (int k = 0; k < CH; k++) acc += row[k] * W[k * CH + t];
    y[g * CH + t] = gelu_exact(acc);
}

__global__ void k_head3(const float* __restrict__ x, const float* __restrict__ W,
                        const float* __restrict__ b, float* __restrict__ out) {
    __shared__ float row[CH];
    int g = blockIdx.x, t = threadIdx.x;
    row[t] = x[g * CH + t];
    __syncthreads();
    if (t < 10) {
        float acc = b[t];
        #pragma unroll 8
        for (int k = 0; k < CH; k++) acc += row[k] * W[k * 10 + t];
        out[g * 10 + t] = acc;
    }
}

// ---------------- driver ----------------
static float* devptr_f(const void* sym) { void* p = nullptr; cudaGetSymbolAddress(&p, sym); return (float*)p; }
static int* devptr_i(const void* sym) { void* p = nullptr; cudaGetSymbolAddress(&p, sym); return (int*)p; }
static __half* devptr_h(const void* sym) { void* p = nullptr; cudaGetSymbolAddress(&p, sym); return (__half*)p; }

extern "C" void kernel_launch(void* const* d_in, const int* in_sizes, int n_in,
                              void* d_out, int out_size) {
    const float* x      = (const float*)d_in[0];
    const int*   eidx   = (const int*)d_in[1];
    const int*   batch  = (const int*)d_in[2];
    const float* Wb0 = (const float*)d_in[4];
    const float* bb0 = (const float*)d_in[5];
    const float* gb0 = (const float*)d_in[6];
    const float* betab0 = (const float*)d_in[7];
    const float* Wb1 = (const float*)d_in[8];
    const float* bb1 = (const float*)d_in[9];
    const float* Wa0 = (const float*)d_in[10];
    const float* ba0 = (const float*)d_in[11];
    const float* ga0 = (const float*)d_in[12];
    const float* bea0 = (const float*)d_in[13];
    const float* Wa1 = (const float*)d_in[14];
    const float* ba1 = (const float*)d_in[15];
    const float* ga1 = (const float*)d_in[16];
    const float* bea1 = (const float*)d_in[17];
    const float* Wa2 = (const float*)d_in[18];
    const float* ba2 = (const float*)d_in[19];
    const float* Wh0 = (const float*)d_in[20];
    const float* bh0 = (const float*)d_in[21];
    const float* Wh1 = (const float*)d_in[22];
    const float* bh1 = (const float*)d_in[23];
    const float* Wh2 = (const float*)d_in[24];
    const float* bh2 = (const float*)d_in[25];

    int N = in_sizes[0] / CH;
    int E = in_sizes[1] / 2;
    const int* esrc = eidx;
    const int* edst = eidx + E;

    __half* hw  = devptr_h(g_hw);
    float* actA  = devptr_f(g_actA);
    float* actB  = devptr_f(g_actB);
    float* dinv  = devptr_f(g_dinv);
    float* bnsum = devptr_f(g_bnsum);
    float* pool  = devptr_f(g_pool);
    float* y1    = devptr_f(g_y1);
    float* y2    = devptr_f(g_y2);
    int* indeg    = devptr_i(g_indeg);
    int* rowstart = devptr_i(g_rowstart);
    int* fill     = devptr_i(g_fill);
    int* edges    = devptr_i(g_edges);
    int* blocksum = devptr_i(g_blocksum);
    int* blockoff = devptr_i(g_blockoff);

    int gemmGrid = (N + BM - 1) / BM;
    int aggGrid  = (N + 7) / 8;
    int scanB = (N + 1023) / 1024;
    float invN = 1.0f / (float)N;

    // ---- CSR + degree prep ----
    k_init<<<128, 256>>>(indeg, bnsum, pool, N);
    k_count<<<(E + 1023) / 1024, 256>>>(edst, indeg, E);
    k_scan_blk<<<scanB, 1024>>>(indeg, rowstart, blocksum, dinv, N);
    k_scan_top<<<1, 32>>>(blocksum, blockoff, rowstart, scanB, N);
    k_scan_add<<<(N + 255) / 256, 256>>>(rowstart, blockoff, fill, N);

    // Layer-0 GEMM only needs dinv
    k_gemm<<<gemmGrid, 256>>>(x, Wb0, dinv, nullptr, nullptr, nullptr, invN, hw, N);

    k_fillcsr<<<(E + 1023) / 1024, 256>>>(esrc, edst, fill, edges, E);

    // ---- Layer 0 agg (+ BN0 stats) ----
    k_agg<<<aggGrid, 256>>>(hw, edges, rowstart, dinv, bb0, actA, bnsum + 0 * 256, N);

    // ---- Layer 1: conv(gelu(BN0(actA))) -> actB ----
    k_gemm<<<gemmGrid, 256>>>(actA, Wb1, dinv, bnsum + 0 * 256, gb0, betab0, invN, hw, N);
    k_agg<<<aggGrid, 256>>>(hw, edges, rowstart, dinv, bb1, actB, nullptr, N);

    // ---- Layer 2: conv(actB) -> actA (+ BN1 stats) ----
    k_gemm<<<gemmGrid, 256>>>(actB, Wa0, dinv, nullptr, nullptr, nullptr, invN, hw, N);
    k_agg<<<aggGrid, 256>>>(hw, edges, rowstart, dinv, ba0, actA, bnsum + 1 * 256, N);

    // ---- Layer 3: conv(gelu(BN1(actA))) -> actB (+ BN2 stats) ----
    k_gemm<<<gemmGrid, 256>>>(actA, Wa1, dinv, bnsum + 1 * 256, ga0, bea0, invN, hw, N);
    k_agg<<<aggGrid, 256>>>(hw, edges, rowstart, dinv, ba1, actB, bnsum + 2 * 256, N);

    // ---- Layer 4: conv(gelu(BN2(actB))) -> actA ----
    k_gemm<<<gemmGrid, 256>>>(actB, Wa2, dinv, bnsum + 2 * 256, ga1, bea1, invN, hw, N);
    k_agg<<<aggGrid, 256>>>(hw, edges, rowstart, dinv, ba2, actA, nullptr, N);

    // ---- pool + head ----
    k_pool<<<64, 256>>>(actA, batch, pool, pool + NGRAPHS * CH, N);
    k_head1<<<NGRAPHS, CH>>>(pool, pool + NGRAPHS * CH, Wh0, bh0, y1);
    k_head2<<<NGRAPHS, CH>>>(y1, Wh1, bh1, y2);
    k_head3<<<NGRAPHS, CH>>>(y2, Wh2, bh2, (float*)d_out);
}

// round 15
// speedup vs baseline: 1.0309x; 1.0309x over previous
#include <cuda_runtime.h>
#include <cuda_fp16.h>
#include <math.h>

// ---------------- problem constants ----------------
#define NMAX      50000
#define EMAX      800000
#define CH        128
#define NGRAPHS   64
#define BN_EPS    1e-5f

// ---------------- scratch (device globals) ----------------
__device__ __half g_hw[NMAX * CH];    // GEMM output, rows pre-scaled by dinv (fp16)
__device__ float g_actA[NMAX * CH];
__device__ float g_actB[NMAX * CH];
__device__ float g_dinv[NMAX];
__device__ int   g_indeg[NMAX];
__device__ int   g_rowstart[NMAX + 1];
__device__ int   g_fill[NMAX];
__device__ int   g_edges[EMAX];
__device__ int   g_blocksum[64];
__device__ int   g_blockoff[64];
__device__ float g_bnsum[3 * 2 * CH];
__device__ float g_pool[NGRAPHS * CH + NGRAPHS];
__device__ float g_y1[NGRAPHS * CH];
__device__ float g_y2[NGRAPHS * CH];

// ---------------- helpers ----------------
__device__ __forceinline__ float gelu_exact(float x) {
    return 0.5f * x * (1.0f + erff(x * 0.70710678118654752440f));
}

// tanh-form gelu using HW MUFU.TANH (sm_90+)
__device__ __forceinline__ float gelu_fast(float x) {
    float u = x * (0.7978845608028654f + 0.035677408136300125f * x * x);
    float t;
    asm("tanh.approx.f32 %0, %1;" : "=f"(t) : "f"(u));
    return 0.5f * x * (1.0f + t);
}

__device__ __forceinline__ unsigned h2u(__half2 h) { return *reinterpret_cast<unsigned*>(&h); }

__device__ __forceinline__ void ldsm_x4(unsigned r[4], const void* p) {
    unsigned addr = (unsigned)__cvta_generic_to_shared(p);
    asm volatile("ldmatrix.sync.aligned.m8n8.x4.shared.b16 {%0,%1,%2,%3}, [%4];"
                 : "=r"(r[0]), "=r"(r[1]), "=r"(r[2]), "=r"(r[3]) : "r"(addr));
}
__device__ __forceinline__ void ldsm_x4_t(unsigned r[4], const void* p) {
    unsigned addr = (unsigned)__cvta_generic_to_shared(p);
    asm volatile("ldmatrix.sync.aligned.m8n8.x4.trans.shared.b16 {%0,%1,%2,%3}, [%4];"
                 : "=r"(r[0]), "=r"(r[1]), "=r"(r[2]), "=r"(r[3]) : "r"(addr));
}
__device__ __forceinline__ void mma16816(float c[4], const unsigned a[4],
                                         unsigned b0, unsigned b1) {
    asm volatile(
        "mma.sync.aligned.m16n8k16.row.col.f32.f16.f16.f32 "
        "{%0,%1,%2,%3}, {%4,%5,%6,%7}, {%8,%9}, {%0,%1,%2,%3};"
        : "+f"(c[0]), "+f"(c[1]), "+f"(c[2]), "+f"(c[3])
        : "r"(a[0]), "r"(a[1]), "r"(a[2]), "r"(a[3]), "r"(b0), "r"(b1));
}

// ---------------- init ----------------
__global__ void k_init(int* __restrict__ indeg, float* __restrict__ bnsum,
                       float* __restrict__ pool, int N) {
    int i = blockIdx.x * blockDim.x + threadIdx.x;
    int st = gridDim.x * blockDim.x;
    for (int j = i; j < N; j += st) indeg[j] = 0;
    for (int j = i; j < 3 * 2 * CH; j += st) bnsum[j] = 0.f;
    for (int j = i; j < NGRAPHS * CH + NGRAPHS; j += st) pool[j] = 0.f;
}

// ---------------- degree / CSR build ----------------
__global__ void k_count(const int* __restrict__ dst, int* __restrict__ indeg, int E) {
    int i = blockIdx.x * blockDim.x + threadIdx.x;
    if (i < E) atomicAdd(&indeg[dst[i]], 1);
}

__global__ void k_scan_blk(const int* __restrict__ indeg, int* __restrict__ scanned,
                           int* __restrict__ blocksum, float* __restrict__ dinv, int N) {
    __shared__ int wsum[32];
    int tid = threadIdx.x, lane = tid & 31, wid = tid >> 5;
    int idx = blockIdx.x * 1024 + tid;
    int v = (idx < N) ? indeg[idx] : 0;
    if (idx < N) dinv[idx] = rsqrtf((float)(v + 1));
    int x = v;
    #pragma unroll
    for (int off = 1; off < 32; off <<= 1) {
        int y = __shfl_up_sync(0xffffffffu, x, off);
        if (lane >= off) x += y;
    }
    if (lane == 31) wsum[wid] = x;
    __syncthreads();
    if (wid == 0) {
        int w = wsum[lane];
        #pragma unroll
        for (int off = 1; off < 32; off <<= 1) {
            int y = __shfl_up_sync(0xffffffffu, w, off);
            if (lane >= off) w += y;
        }
        wsum[lane] = w;
    }
    __syncthreads();
    int excl = x - v + (wid ? wsum[wid - 1] : 0);
    if (idx < N) scanned[idx] = excl;
    if (tid == 1023) blocksum[blockIdx.x] = excl + v;
}

__global__ void k_scan_top(const int* __restrict__ blocksum, int* __restrict__ blockoff,
                           int* __restrict__ rowstart, int B, int N) {
    int lane = threadIdx.x;
    int run = 0;
    for (int base = 0; base < B; base += 32) {
        int v = (base + lane < B) ? blocksum[base + lane] : 0;
        int x = v;
        #pragma unroll
        for (int off = 1; off < 32; off <<= 1) {
            int y = __shfl_up_sync(0xffffffffu, x, off);
            if (lane >= off) x += y;
        }
        if (base + lane < B) blockoff[base + lane] = x - v + run;
        run += __shfl_sync(0xffffffffu, x, 31);
    }
    if (lane == 0) rowstart[N] = run;
}

__global__ void k_scan_add(int* __restrict__ rowstart, const int* __restrict__ blockoff,
                           int* __restrict__ fill, int N) {
    int idx = blockIdx.x * blockDim.x + threadIdx.x;
    if (idx < N) {
        int v = rowstart[idx] + blockoff[idx >> 10];
        rowstart[idx] = v;
        fill[idx] = v;
    }
}

__global__ void k_fillcsr(const int* __restrict__ src, const int* __restrict__ dst,
                          int* __restrict__ fill, int* __restrict__ edges, int E) {
    int i = blockIdx.x * blockDim.x + threadIdx.x;
    if (i < E) {
        int pos = atomicAdd(&fill[dst[i]], 1);
        edges[pos] = src[i];
    }
}

// ---------------- tensor-core GEMM with optional fused BN+gelu on A ----------------
// out[r] = (half) dinv[r] * ( f(A[r]) @ W ),  f = gelu(A*scl+shf) if bnsum else identity
#define BM 128

__global__ void __launch_bounds__(256, 2)
k_gemm(const float* __restrict__ A, const float* __restrict__ W,
       const float* __restrict__ dinv,
       const float* __restrict__ bnsum, const float* __restrict__ gamma,
       const float* __restrict__ beta, float invN,
       __half* __restrict__ out, int N) {
    __shared__ __half sA[128][72];
    __shared__ __half sB[64][136];
    __shared__ float scl[CH], shf[CH];

    int tid = threadIdx.x;
    int lane = tid & 31, wid = tid >> 5;
    int warpM = wid >> 1, warpN = wid & 1;
    int rowBase = blockIdx.x * BM;

    if (bnsum) {
        if (tid < CH) {
            float mean = bnsum[tid] * invN;
            float var = bnsum[CH + tid] * invN - mean * mean;
            float s = gamma[tid] * rsqrtf(var + BN_EPS);
            scl[tid] = s;
            shf[tid] = beta[tid] - mean * s;
        }
        __syncthreads();
    }

    float acc[2][8][4];
    #pragma unroll
    for (int mi = 0; mi < 2; mi++)
        #pragma unroll
        for (int ni = 0; ni < 8; ni++)
            #pragma unroll
            for (int j = 0; j < 4; j++) acc[mi][ni][j] = 0.f;

    for (int kt = 0; kt < CH; kt += 64) {
        #pragma unroll
        for (int i = 0; i < 8; i++) {
            int p = tid + i * 256;
            int r = p >> 4, c4 = p & 15;
            float4 v = make_float4(0.f, 0.f, 0.f, 0.f);
            int grow = rowBase + r;
            if (grow < N) v = *(const float4*)&A[grow * CH + kt + c4 * 4];
            if (bnsum) {
                int c = kt + c4 * 4;
                v.x = gelu_fast(v.x * scl[c + 0] + shf[c + 0]);
                v.y = gelu_fast(v.y * scl[c + 1] + shf[c + 1]);
                v.z = gelu_fast(v.z * scl[c + 2] + shf[c + 2]);
                v.w = gelu_fast(v.w * scl[c + 3] + shf[c + 3]);
            }
            __half2 h0 = __floats2half2_rn(v.x, v.y);
            __half2 h1 = __floats2half2_rn(v.z, v.w);
            *(uint2*)&sA[r][c4 * 4] = make_uint2(h2u(h0), h2u(h1));
        }
        #pragma unroll
        for (int i = 0; i < 8; i++) {
            int p = tid + i * 256;
            int r = p >> 5, c4 = p & 31;
            float4 v = *(const float4*)&W[(kt + r) * CH + c4 * 4];
            __half2 h0 = __floats2half2_rn(v.x, v.y);
            __half2 h1 = __floats2half2_rn(v.z, v.w);
            *(uint2*)&sB[r][c4 * 4] = make_uint2(h2u(h0), h2u(h1));
        }
        __syncthreads();

        #pragma unroll
        for (int ks = 0; ks < 64; ks += 16) {
            unsigned af[2][4];
            #pragma unroll
            for (int mi = 0; mi < 2; mi++) {
                int r = warpM * 32 + mi * 16 + (lane & 15);
                int c = ks + (lane >> 4) * 8;
                ldsm_x4(af[mi], &sA[r][c]);
            }
            unsigned bf[4][4];
            #pragma unroll
            for (int nj = 0; nj < 4; nj++) {
                int r = ks + (lane & 15);
                int c = warpN * 64 + nj * 16 + (lane >> 4) * 8;
                ldsm_x4_t(bf[nj], &sB[r][c]);
            }
            #pragma unroll
            for (int mi = 0; mi < 2; mi++)
                #pragma unroll
                for (int ni = 0; ni < 8; ni++)
                    mma16816(acc[mi][ni], af[mi],
                             bf[ni >> 1][(ni & 1) * 2], bf[ni >> 1][(ni & 1) * 2 + 1]);
        }
        __syncthreads();
    }

    #pragma unroll
    for (int mi = 0; mi < 2; mi++) {
        int r0 = rowBase + warpM * 32 + mi * 16 + (lane >> 2);
        int r1 = r0 + 8;
        float d0 = (r0 < N) ? dinv[r0] : 0.f;
        float d1 = (r1 < N) ? dinv[r1] : 0.f;
        #pragma unroll
        for (int ni = 0; ni < 8; ni++) {
            int col = warpN * 64 + ni * 8 + (lane & 3) * 2;
            if (r0 < N) {
                __half2 h = __floats2half2_rn(acc[mi][ni][0] * d0, acc[mi][ni][1] * d0);
                *(__half2*)&out[r0 * CH + col] = h;
            }
            if (r1 < N) {
                __half2 h = __floats2half2_rn(acc[mi][ni][2] * d1, acc[mi][ni][3] * d1);
                *(__half2*)&out[r1 * CH + col] = h;
            }
        }
    }
}

// ---------------- aggregation (fp16 gather, MLP-8 batches), fused BN stats ----------------
__device__ __forceinline__ void acc_h4(float4& a, uint2 v) {
    __half2 h0 = *reinterpret_cast<__half2*>(&v.x);
    __half2 h1 = *reinterpret_cast<__half2*>(&v.y);
    float2 f0 = __half22float2(h0);
    float2 f1 = __half22float2(h1);
    a.x += f0.x; a.y += f0.y; a.z += f1.x; a.w += f1.y;
}

__global__ void k_agg(const __half* __restrict__ hws, const int* __restrict__ edges,
                      const int* __restrict__ rowstart, const float* __restrict__ dinv,
                      const float* __restrict__ bias, float* __restrict__ outf,
                      float* __restrict__ stats, int N) {
    __shared__ float sh[8][CH];
    int wId = threadIdx.x >> 5;
    int lane = threadIdx.x & 31;
    int node = blockIdx.x * 8 + wId;
    bool valid = node < N;

    const uint2* base = (const uint2*)hws;
    float4 acc = make_float4(0.f, 0.f, 0.f, 0.f);
    float4 acc2 = make_float4(0.f, 0.f, 0.f, 0.f);
    int s = 0, e = 0;
    float d = 0.f;
    if (valid) {
        acc_h4(acc, base[node * 32 + lane]);   // self loop (pre-scaled by dinv)
        s = rowstart[node]; e = rowstart[node + 1];
        d = dinv[node];
    }
    int i = s;
    for (; i + 7 < e; i += 8) {
        int idx[8];
        #pragma unroll
        for (int j = 0; j < 8; j++) idx[j] = __ldg(&edges[i + j]);
        uint2 v[8];
        #pragma unroll
        for (int j = 0; j < 8; j++) v[j] = base[idx[j] * 32 + lane];
        #pragma unroll
        for (int j = 0; j < 8; j += 2) { acc_h4(acc, v[j]); acc_h4(acc2, v[j + 1]); }
    }
    for (; i + 1 < e; i += 2) {
        int i0 = __ldg(&edges[i]);
        int i1 = __ldg(&edges[i + 1]);
        uint2 v0 = base[i0 * 32 + lane];
        uint2 v1 = base[i1 * 32 + lane];
        acc_h4(acc, v0); acc_h4(acc2, v1);
    }
    if (i < e) acc_h4(acc, base[__ldg(&edges[i]) * 32 + lane]);
    acc.x += acc2.x; acc.y += acc2.y; acc.z += acc2.z; acc.w += acc2.w;

    float4 o = make_float4(0.f, 0.f, 0.f, 0.f);
    if (valid) {
        float4 bb = ((const float4*)bias)[lane];
        o.x = acc.x * d + bb.x; o.y = acc.y * d + bb.y;
        o.z = acc.z * d + bb.z; o.w = acc.w * d + bb.w;
        ((float4*)outf)[node * 32 + lane] = o;
    }
    if (stats) {
        *(float4*)&sh[wId][lane * 4] = o;
        __syncthreads();
        int t = threadIdx.x;
        int c = t & 127;
        bool sq = t >= 128;
        float a2 = 0.f;
        #pragma unroll
        for (int w = 0; w < 8; w++) {
            float v = sh[w][c];
            a2 += sq ? v * v : v;
        }
        atomicAdd(&stats[sq ? CH + c : c], a2);
    }
}

// ---------------- pooling ----------------
__global__ void k_pool(const float* __restrict__ h, const int* __restrict__ batch,
                       float* __restrict__ psum, float* __restrict__ pcnt, int N) {
    __shared__ float sh[NGRAPHS * CH];
    __shared__ float shc[NGRAPHS];
    int tid = threadIdx.x;
    for (int i = tid; i < NGRAPHS * CH; i += 256) sh[i] = 0.f;
    if (tid < NGRAPHS) shc[tid] = 0.f;
    __syncthreads();
    int rpb = (N + gridDim.x - 1) / gridDim.x;
    int r0 = blockIdx.x * rpb;
    int r1 = min(r0 + rpb, N);
    int col = tid & 127;
    for (int r = r0 + (tid >> 7); r < r1; r += 2) {
        int g = batch[r];
        atomicAdd(&sh[g * CH + col], h[r * CH + col]);
        if (col == 0) atomicAdd(&shc[g], 1.0f);
    }
    __syncthreads();
    for (int i = tid; i < NGRAPHS * CH; i += 256)
        if (sh[i] != 0.f) atomicAdd(&psum[i], sh[i]);
    if (tid < NGRAPHS && shc[tid] != 0.f) atomicAdd(&pcnt[tid], shc[tid]);
}

// ---------------- head ----------------
__global__ void k_head1(const float* __restrict__ psum, const float* __restrict__ pcnt,
                        const float* __restrict__ W, const float* __restrict__ b,
                        float* __restrict__ y) {
    __shared__ float row[CH];
    int g = blockIdx.x, t = threadIdx.x;
    float cnt = fmaxf(pcnt[g], 1.0f);
    row[t] = psum[g * CH + t] / cnt;
    __syncthreads();
    float acc = b[t];
    #pragma unroll 8
    for (int k = 0; k < CH; k++) acc += row[k] * W[k * CH + t];
    y[g * CH + t] = gelu_exact(acc);
}

__global__ void k_head2(const float* __restrict__ x, const float* __restrict__ W,
                        const float* __restrict__ b, float* __restrict__ y) {
    __shared__ float row[CH];
    int g = blockIdx.x, t = threadIdx.x;
    row[t] = x[g * CH + t];
    __syncthreads();
    float acc = b[t];
    #pragma unroll 8
    for (int k = 0; k < CH; k++) acc += row[k] * W[k * CH + t];
    y[g * CH + t] = gelu_exact(acc);
}

__global__ void k_head3(const float* __restrict__ x, const float* __restrict__ W,
                        const float* __restrict__ b, float* __restrict__ out) {
    __shared__ float row[CH];
    int g = blockIdx.x, t = threadIdx.x;
    row[t] = x[g * CH + t];
    __syncthreads();
    if (t < 10) {
        float acc = b[t];
        #pragma unroll 8
        for (int k = 0; k < CH; k++) acc += row[k] * W[k * 10 + t];
        out[g * 10 + t] = acc;
    }
}

// ---------------- driver ----------------
static float* devptr_f(const void* sym) { void* p = nullptr; cudaGetSymbolAddress(&p, sym); return (float*)p; }
static int* devptr_i(const void* sym) { void* p = nullptr; cudaGetSymbolAddress(&p, sym); return (int*)p; }
static __half* devptr_h(const void* sym) { void* p = nullptr; cudaGetSymbolAddress(&p, sym); return (__half*)p; }

extern "C" void kernel_launch(void* const* d_in, const int* in_sizes, int n_in,
                              void* d_out, int out_size) {
    const float* x      = (const float*)d_in[0];
    const int*   eidx   = (const int*)d_in[1];
    const int*   batch  = (const int*)d_in[2];
    const float* Wb0 = (const float*)d_in[4];
    const float* bb0 = (const float*)d_in[5];
    const float* gb0 = (const float*)d_in[6];
    const float* betab0 = (const float*)d_in[7];
    const float* Wb1 = (const float*)d_in[8];
    const float* bb1 = (const float*)d_in[9];
    const float* Wa0 = (const float*)d_in[10];
    const float* ba0 = (const float*)d_in[11];
    const float* ga0 = (const float*)d_in[12];
    const float* bea0 = (const float*)d_in[13];
    const float* Wa1 = (const float*)d_in[14];
    const float* ba1 = (const float*)d_in[15];
    const float* ga1 = (const float*)d_in[16];
    const float* bea1 = (const float*)d_in[17];
    const float* Wa2 = (const float*)d_in[18];
    const float* ba2 = (const float*)d_in[19];
    const float* Wh0 = (const float*)d_in[20];
    const float* bh0 = (const float*)d_in[21];
    const float* Wh1 = (const float*)d_in[22];
    const float* bh1 = (const float*)d_in[23];
    const float* Wh2 = (const float*)d_in[24];
    const float* bh2 = (const float*)d_in[25];

    int N = in_sizes[0] / CH;
    int E = in_sizes[1] / 2;
    const int* esrc = eidx;
    const int* edst = eidx + E;

    __half* hw  = devptr_h(g_hw);
    float* actA  = devptr_f(g_actA);
    float* actB  = devptr_f(g_actB);
    float* dinv  = devptr_f(g_dinv);
    float* bnsum = devptr_f(g_bnsum);
    float* pool  = devptr_f(g_pool);
    float* y1    = devptr_f(g_y1);
    float* y2    = devptr_f(g_y2);
    int* indeg    = devptr_i(g_indeg);
    int* rowstart = devptr_i(g_rowstart);
    int* fill     = devptr_i(g_fill);
    int* edges    = devptr_i(g_edges);
    int* blocksum = devptr_i(g_blocksum);
    int* blockoff = devptr_i(g_blockoff);

    int gemmGrid = (N + BM - 1) / BM;
    int aggGrid  = (N + 7) / 8;
    int scanB = (N + 1023) / 1024;
    float invN = 1.0f / (float)N;

    // ---- CSR + degree prep ----
    k_init<<<128, 256>>>(indeg, bnsum, pool, N);
    k_count<<<(E + 255) / 256, 256>>>(edst, indeg, E);
    k_scan_blk<<<scanB, 1024>>>(indeg, rowstart, blocksum, dinv, N);
    k_scan_top<<<1, 32>>>(blocksum, blockoff, rowstart, scanB, N);
    k_scan_add<<<(N + 255) / 256, 256>>>(rowstart, blockoff, fill, N);

    // ---- Layer 0 GEMM (only needs dinv) — launch slot 6 so ncu -s 5 captures it ----
    k_gemm<<<gemmGrid, 256>>>(x, Wb0, dinv, nullptr, nullptr, nullptr, invN, hw, N);

    k_fillcsr<<<(E + 255) / 256, 256>>>(esrc, edst, fill, edges, E);

    // ---- Layer 0 agg (+ BN0 stats) ----
    k_agg<<<aggGrid, 256>>>(hw, edges, rowstart, dinv, bb0, actA, bnsum + 0 * 256, N);

    // ---- Layer 1: conv(gelu(BN0(actA))) -> actB ----
    k_gemm<<<gemmGrid, 256>>>(actA, Wb1, dinv, bnsum + 0 * 256, gb0, betab0, invN, hw, N);
    k_agg<<<aggGrid, 256>>>(hw, edges, rowstart, dinv, bb1, actB, nullptr, N);

    // ---- Layer 2: conv(actB) -> actA (+ BN1 stats) ----
    k_gemm<<<gemmGrid, 256>>>(actB, Wa0, dinv, nullptr, nullptr, nullptr, invN, hw, N);
    k_agg<<<aggGrid, 256>>>(hw, edges, rowstart, dinv, ba0, actA, bnsum + 1 * 256, N);

    // ---- Layer 3: conv(gelu(BN1(actA))) -> actB (+ BN2 stats) ----
    k_gemm<<<gemmGrid, 256>>>(actA, Wa1, dinv, bnsum + 1 * 256, ga0, bea0, invN, hw, N);
    k_agg<<<aggGrid, 256>>>(hw, edges, rowstart, dinv, ba1, actB, bnsum + 2 * 256, N);

    // ---- Layer 4: conv(gelu(BN2(actB))) -> actA ----
    k_gemm<<<gemmGrid, 256>>>(actB, Wa2, dinv, bnsum + 2 * 256, ga1, bea1, invN, hw, N);
    k_agg<<<aggGrid, 256>>>(hw, edges, rowstart, dinv, ba2, actA, nullptr, N);

    // ---- pool + head ----
    k_pool<<<64, 256>>>(actA, batch, pool, pool + NGRAPHS * CH, N);
    k_head1<<<NGRAPHS, CH>>>(pool, pool + NGRAPHS * CH, Wh0, bh0, y1);
    k_head2<<<NGRAPHS, CH>>>(y1, Wh1, bh1, y2);
    k_head3<<<NGRAPHS, CH>>>(y2, Wh2, bh2, (float*)d_out);
}

// round 16
// speedup vs baseline: 1.4438x; 1.4005x over previous
#include <cuda_runtime.h>
#include <cuda_fp16.h>
#include <math.h>

// ---------------- problem constants ----------------
#define NMAX      50000
#define EMAX      800000
#define CH        128
#define NGRAPHS   64
#define BN_EPS    1e-5f

// ---------------- scratch (device globals) ----------------
__device__ __half g_hw[NMAX * CH];    // GEMM output, rows pre-scaled by dinv (fp16)
__device__ float g_actA[NMAX * CH];
__device__ float g_actB[NMAX * CH];
__device__ float g_dinv[NMAX];
__device__ int   g_indeg[NMAX];
__device__ int   g_rowstart[NMAX + 1];
__device__ int   g_fill[NMAX];
__device__ int   g_edges[EMAX];
__device__ int   g_blocksum[64];
__device__ int   g_blockoff[64];
__device__ float g_bnsum[3 * 2 * CH];
__device__ float g_pool[NGRAPHS * CH + NGRAPHS];
__device__ float g_y1[NGRAPHS * CH];
__device__ float g_y2[NGRAPHS * CH];

// ---------------- helpers ----------------
__device__ __forceinline__ float gelu_exact(float x) {
    return 0.5f * x * (1.0f + erff(x * 0.70710678118654752440f));
}

// tanh-form gelu using HW MUFU.TANH (sm_90+)
__device__ __forceinline__ float gelu_fast(float x) {
    float u = x * (0.7978845608028654f + 0.035677408136300125f * x * x);
    float t;
    asm("tanh.approx.f32 %0, %1;" : "=f"(t) : "f"(u));
    return 0.5f * x * (1.0f + t);
}

__device__ __forceinline__ unsigned h2u(__half2 h) { return *reinterpret_cast<unsigned*>(&h); }

__device__ __forceinline__ void ldsm_x4(unsigned r[4], const void* p) {
    unsigned addr = (unsigned)__cvta_generic_to_shared(p);
    asm volatile("ldmatrix.sync.aligned.m8n8.x4.shared.b16 {%0,%1,%2,%3}, [%4];"
                 : "=r"(r[0]), "=r"(r[1]), "=r"(r[2]), "=r"(r[3]) : "r"(addr));
}
__device__ __forceinline__ void ldsm_x4_t(unsigned r[4], const void* p) {
    unsigned addr = (unsigned)__cvta_generic_to_shared(p);
    asm volatile("ldmatrix.sync.aligned.m8n8.x4.trans.shared.b16 {%0,%1,%2,%3}, [%4];"
                 : "=r"(r[0]), "=r"(r[1]), "=r"(r[2]), "=r"(r[3]) : "r"(addr));
}
__device__ __forceinline__ void mma16816(float c[4], const unsigned a[4],
                                         unsigned b0, unsigned b1) {
    asm volatile(
        "mma.sync.aligned.m16n8k16.row.col.f32.f16.f16.f32 "
        "{%0,%1,%2,%3}, {%4,%5,%6,%7}, {%8,%9}, {%0,%1,%2,%3};"
        : "+f"(c[0]), "+f"(c[1]), "+f"(c[2]), "+f"(c[3])
        : "r"(a[0]), "r"(a[1]), "r"(a[2]), "r"(a[3]), "r"(b0), "r"(b1));
}

// ---------------- init ----------------
__global__ void k_init(int* __restrict__ indeg, float* __restrict__ bnsum,
                       float* __restrict__ pool, int N) {
    int i = blockIdx.x * blockDim.x + threadIdx.x;
    int st = gridDim.x * blockDim.x;
    for (int j = i; j < N; j += st) indeg[j] = 0;
    for (int j = i; j < 3 * 2 * CH; j += st) bnsum[j] = 0.f;
    for (int j = i; j < NGRAPHS * CH + NGRAPHS; j += st) pool[j] = 0.f;
}

// ---------------- degree / CSR build ----------------
__global__ void k_count(const int* __restrict__ dst, int* __restrict__ indeg, int E) {
    int i = blockIdx.x * blockDim.x + threadIdx.x;
    if (i < E) atomicAdd(&indeg[dst[i]], 1);
}

__global__ void k_scan_blk(const int* __restrict__ indeg, int* __restrict__ scanned,
                           int* __restrict__ blocksum, float* __restrict__ dinv, int N) {
    __shared__ int wsum[32];
    int tid = threadIdx.x, lane = tid & 31, wid = tid >> 5;
    int idx = blockIdx.x * 1024 + tid;
    int v = (idx < N) ? indeg[idx] : 0;
    if (idx < N) dinv[idx] = rsqrtf((float)(v + 1));
    int x = v;
    #pragma unroll
    for (int off = 1; off < 32; off <<= 1) {
        int y = __shfl_up_sync(0xffffffffu, x, off);
        if (lane >= off) x += y;
    }
    if (lane == 31) wsum[wid] = x;
    __syncthreads();
    if (wid == 0) {
        int w = wsum[lane];
        #pragma unroll
        for (int off = 1; off < 32; off <<= 1) {
            int y = __shfl_up_sync(0xffffffffu, w, off);
            if (lane >= off) w += y;
        }
        wsum[lane] = w;
    }
    __syncthreads();
    int excl = x - v + (wid ? wsum[wid - 1] : 0);
    if (idx < N) scanned[idx] = excl;
    if (tid == 1023) blocksum[blockIdx.x] = excl + v;
}

__global__ void k_scan_top(const int* __restrict__ blocksum, int* __restrict__ blockoff,
                           int* __restrict__ rowstart, int B, int N) {
    int lane = threadIdx.x;
    int run = 0;
    for (int base = 0; base < B; base += 32) {
        int v = (base + lane < B) ? blocksum[base + lane] : 0;
        int x = v;
        #pragma unroll
        for (int off = 1; off < 32; off <<= 1) {
            int y = __shfl_up_sync(0xffffffffu, x, off);
            if (lane >= off) x += y;
        }
        if (base + lane < B) blockoff[base + lane] = x - v + run;
        run += __shfl_sync(0xffffffffu, x, 31);
    }
    if (lane == 0) rowstart[N] = run;
}

__global__ void k_scan_add(int* __restrict__ rowstart, const int* __restrict__ blockoff,
                           int* __restrict__ fill, int N) {
    int idx = blockIdx.x * blockDim.x + threadIdx.x;
    if (idx < N) {
        int v = rowstart[idx] + blockoff[idx >> 10];
        rowstart[idx] = v;
        fill[idx] = v;
    }
}

__global__ void k_fillcsr(const int* __restrict__ src, const int* __restrict__ dst,
                          int* __restrict__ fill, int* __restrict__ edges, int E) {
    int i = blockIdx.x * blockDim.x + threadIdx.x;
    if (i < E) {
        int pos = atomicAdd(&fill[dst[i]], 1);
        edges[pos] = src[i];
    }
}

// ---------------- tensor-core GEMM with optional fused BN+gelu on A ----------------
// out[r] = (half) dinv[r] * ( f(A[r]) @ W ),  f = gelu(A*scl+shf) if bnsum else identity
#define BM 128

__global__ void __launch_bounds__(256, 2)
k_gemm(const float* __restrict__ A, const float* __restrict__ W,
       const float* __restrict__ dinv,
       const float* __restrict__ bnsum, const float* __restrict__ gamma,
       const float* __restrict__ beta, float invN,
       __half* __restrict__ out, int N) {
    __shared__ __half sA[128][72];
    __shared__ __half sB[64][136];
    __shared__ float scl[CH], shf[CH];

    int tid = threadIdx.x;
    int lane = tid & 31, wid = tid >> 5;
    int warpM = wid >> 1, warpN = wid & 1;
    int rowBase = blockIdx.x * BM;

    if (bnsum) {
        if (tid < CH) {
            float mean = bnsum[tid] * invN;
            float var = bnsum[CH + tid] * invN - mean * mean;
            float s = gamma[tid] * rsqrtf(var + BN_EPS);
            scl[tid] = s;
            shf[tid] = beta[tid] - mean * s;
        }
        __syncthreads();
    }

    float acc[2][8][4];
    #pragma unroll
    for (int mi = 0; mi < 2; mi++)
        #pragma unroll
        for (int ni = 0; ni < 8; ni++)
            #pragma unroll
            for (int j = 0; j < 4; j++) acc[mi][ni][j] = 0.f;

    for (int kt = 0; kt < CH; kt += 64) {
        #pragma unroll
        for (int i = 0; i < 8; i++) {
            int p = tid + i * 256;
            int r = p >> 4, c4 = p & 15;
            float4 v = make_float4(0.f, 0.f, 0.f, 0.f);
            int grow = rowBase + r;
            if (grow < N) v = *(const float4*)&A[grow * CH + kt + c4 * 4];
            if (bnsum) {
                int c = kt + c4 * 4;
                v.x = gelu_fast(v.x * scl[c + 0] + shf[c + 0]);
                v.y = gelu_fast(v.y * scl[c + 1] + shf[c + 1]);
                v.z = gelu_fast(v.z * scl[c + 2] + shf[c + 2]);
                v.w = gelu_fast(v.w * scl[c + 3] + shf[c + 3]);
            }
            __half2 h0 = __floats2half2_rn(v.x, v.y);
            __half2 h1 = __floats2half2_rn(v.z, v.w);
            *(uint2*)&sA[r][c4 * 4] = make_uint2(h2u(h0), h2u(h1));
        }
        #pragma unroll
        for (int i = 0; i < 8; i++) {
            int p = tid + i * 256;
            int r = p >> 5, c4 = p & 31;
            float4 v = *(const float4*)&W[(kt + r) * CH + c4 * 4];
            __half2 h0 = __floats2half2_rn(v.x, v.y);
            __half2 h1 = __floats2half2_rn(v.z, v.w);
            *(uint2*)&sB[r][c4 * 4] = make_uint2(h2u(h0), h2u(h1));
        }
        __syncthreads();

        #pragma unroll
        for (int ks = 0; ks < 64; ks += 16) {
            unsigned af[2][4];
            #pragma unroll
            for (int mi = 0; mi < 2; mi++) {
                int r = warpM * 32 + mi * 16 + (lane & 15);
                int c = ks + (lane >> 4) * 8;
                ldsm_x4(af[mi], &sA[r][c]);
            }
            unsigned bf[4][4];
            #pragma unroll
            for (int nj = 0; nj < 4; nj++) {
                int r = ks + (lane & 15);
                int c = warpN * 64 + nj * 16 + (lane >> 4) * 8;
                ldsm_x4_t(bf[nj], &sB[r][c]);
            }
            #pragma unroll
            for (int mi = 0; mi < 2; mi++)
                #pragma unroll
                for (int ni = 0; ni < 8; ni++)
                    mma16816(acc[mi][ni], af[mi],
                             bf[ni >> 1][(ni & 1) * 2], bf[ni >> 1][(ni & 1) * 2 + 1]);
        }
        __syncthreads();
    }

    #pragma unroll
    for (int mi = 0; mi < 2; mi++) {
        int r0 = rowBase + warpM * 32 + mi * 16 + (lane >> 2);
        int r1 = r0 + 8;
        float d0 = (r0 < N) ? dinv[r0] : 0.f;
        float d1 = (r1 < N) ? dinv[r1] : 0.f;
        #pragma unroll
        for (int ni = 0; ni < 8; ni++) {
            int col = warpN * 64 + ni * 8 + (lane & 3) * 2;
            if (r0 < N) {
                __half2 h = __floats2half2_rn(acc[mi][ni][0] * d0, acc[mi][ni][1] * d0);
                *(__half2*)&out[r0 * CH + col] = h;
            }
            if (r1 < N) {
                __half2 h = __floats2half2_rn(acc[mi][ni][2] * d1, acc[mi][ni][3] * d1);
                *(__half2*)&out[r1 * CH + col] = h;
            }
        }
    }
}

// ---------------- aggregation (fp16 gather, MLP-8 batches) ----------------
// optional fused BN stats (stats != null) OR fused mean-pool (psum != null)
__device__ __forceinline__ void acc_h4(float4& a, uint2 v) {
    __half2 h0 = *reinterpret_cast<__half2*>(&v.x);
    __half2 h1 = *reinterpret_cast<__half2*>(&v.y);
    float2 f0 = __half22float2(h0);
    float2 f1 = __half22float2(h1);
    a.x += f0.x; a.y += f0.y; a.z += f1.x; a.w += f1.y;
}

__global__ void k_agg(const __half* __restrict__ hws, const int* __restrict__ edges,
                      const int* __restrict__ rowstart, const float* __restrict__ dinv,
                      const float* __restrict__ bias, float* __restrict__ outf,
                      float* __restrict__ stats,
                      const int* __restrict__ batch, float* __restrict__ psum,
                      float* __restrict__ pcnt, int N) {
    __shared__ float sh[8][CH];
    __shared__ int gid[8];
    int wId = threadIdx.x >> 5;
    int lane = threadIdx.x & 31;
    int node = blockIdx.x * 8 + wId;
    bool valid = node < N;

    const uint2* base = (const uint2*)hws;
    float4 acc = make_float4(0.f, 0.f, 0.f, 0.f);
    float4 acc2 = make_float4(0.f, 0.f, 0.f, 0.f);
    int s = 0, e = 0;
    float d = 0.f;
    if (valid) {
        acc_h4(acc, base[node * 32 + lane]);   // self loop (pre-scaled by dinv)
        s = rowstart[node]; e = rowstart[node + 1];
        d = dinv[node];
    }
    int i = s;
    for (; i + 7 < e; i += 8) {
        int idx[8];
        #pragma unroll
        for (int j = 0; j < 8; j++) idx[j] = __ldg(&edges[i + j]);
        uint2 v[8];
        #pragma unroll
        for (int j = 0; j < 8; j++) v[j] = base[idx[j] * 32 + lane];
        #pragma unroll
        for (int j = 0; j < 8; j += 2) { acc_h4(acc, v[j]); acc_h4(acc2, v[j + 1]); }
    }
    for (; i + 1 < e; i += 2) {
        int i0 = __ldg(&edges[i]);
        int i1 = __ldg(&edges[i + 1]);
        uint2 v0 = base[i0 * 32 + lane];
        uint2 v1 = base[i1 * 32 + lane];
        acc_h4(acc, v0); acc_h4(acc2, v1);
    }
    if (i < e) acc_h4(acc, base[__ldg(&edges[i]) * 32 + lane]);
    acc.x += acc2.x; acc.y += acc2.y; acc.z += acc2.z; acc.w += acc2.w;

    float4 o = make_float4(0.f, 0.f, 0.f, 0.f);
    if (valid) {
        float4 bb = ((const float4*)bias)[lane];
        o.x = acc.x * d + bb.x; o.y = acc.y * d + bb.y;
        o.z = acc.z * d + bb.z; o.w = acc.w * d + bb.w;
        if (outf) ((float4*)outf)[node * 32 + lane] = o;
    }
    if (stats) {
        *(float4*)&sh[wId][lane * 4] = o;
        __syncthreads();
        int t = threadIdx.x;
        int c = t & 127;
        bool sq = t >= 128;
        float a2 = 0.f;
        #pragma unroll
        for (int w = 0; w < 8; w++) {
            float v = sh[w][c];
            a2 += sq ? v * v : v;
        }
        atomicAdd(&stats[sq ? CH + c : c], a2);
    }
    if (psum) {
        *(float4*)&sh[wId][lane * 4] = o;     // zeros for invalid nodes
        if (lane == 0) gid[wId] = valid ? __ldg(&batch[node]) : -1;
        __syncthreads();
        int t = threadIdx.x;
        if (t < 128) {
            // batch is sorted: nodes in this block span 1-2 graphs; run-length flush
            float a2 = 0.f;
            int cur = -2;
            #pragma unroll
            for (int w = 0; w < 8; w++) {
                int g = gid[w];
                if (g != cur) {
                    if (cur >= 0) atomicAdd(&psum[cur * CH + t], a2);
                    cur = g; a2 = 0.f;
                }
                a2 += sh[w][t];
            }
            if (cur >= 0) atomicAdd(&psum[cur * CH + t], a2);
        } else if (t == 128) {
            float c = 0.f;
            int cur = -2;
            #pragma unroll
            for (int w = 0; w < 8; w++) {
                int g = gid[w];
                if (g != cur) {
                    if (cur >= 0) atomicAdd(&pcnt[cur], c);
                    cur = g; c = 0.f;
                }
                if (g >= 0) c += 1.f;
            }
            if (cur >= 0) atomicAdd(&pcnt[cur], c);
        }
    }
}

// ---------------- head ----------------
__global__ void k_head1(const float* __restrict__ psum, const float* __restrict__ pcnt,
                        const float* __restrict__ W, const float* __restrict__ b,
                        float* __restrict__ y) {
    __shared__ float row[CH];
    int g = blockIdx.x, t = threadIdx.x;
    float cnt = fmaxf(pcnt[g], 1.0f);
    row[t] = psum[g * CH + t] / cnt;
    __syncthreads();
    float acc = b[t];
    #pragma unroll 8
    for (int k = 0; k < CH; k++) acc += row[k] * W[k * CH + t];
    y[g * CH + t] = gelu_exact(acc);
}

__global__ void k_head2(const float* __restrict__ x, const float* __restrict__ W,
                        const float* __restrict__ b, float* __restrict__ y) {
    __shared__ float row[CH];
    int g = blockIdx.x, t = threadIdx.x;
    row[t] = x[g * CH + t];
    __syncthreads();
    float acc = b[t];
    #pragma unroll 8
    for (int k = 0; k < CH; k++) acc += row[k] * W[k * CH + t];
    y[g * CH + t] = gelu_exact(acc);
}

__global__ void k_head3(const float* __restrict__ x, const float* __restrict__ W,
                        const float* __restrict__ b, float* __restrict__ out) {
    __shared__ float row[CH];
    int g = blockIdx.x, t = threadIdx.x;
    row[t] = x[g * CH + t];
    __syncthreads();
    if (t < 10) {
        float acc = b[t];
        #pragma unroll 8
        for (int k = 0; k < CH; k++) acc += row[k] * W[k * 10 + t];
        out[g * 10 + t] = acc;
    }
}

// ---------------- driver ----------------
static float* devptr_f(const void* sym) { void* p = nullptr; cudaGetSymbolAddress(&p, sym); return (float*)p; }
static int* devptr_i(const void* sym) { void* p = nullptr; cudaGetSymbolAddress(&p, sym); return (int*)p; }
static __half* devptr_h(const void* sym) { void* p = nullptr; cudaGetSymbolAddress(&p, sym); return (__half*)p; }

extern "C" void kernel_launch(void* const* d_in, const int* in_sizes, int n_in,
                              void* d_out, int out_size) {
    const float* x      = (const float*)d_in[0];
    const int*   eidx   = (const int*)d_in[1];
    const int*   batch  = (const int*)d_in[2];
    const float* Wb0 = (const float*)d_in[4];
    const float* bb0 = (const float*)d_in[5];
    const float* gb0 = (const float*)d_in[6];
    const float* betab0 = (const float*)d_in[7];
    const float* Wb1 = (const float*)d_in[8];
    const float* bb1 = (const float*)d_in[9];
    const float* Wa0 = (const float*)d_in[10];
    const float* ba0 = (const float*)d_in[11];
    const float* ga0 = (const float*)d_in[12];
    const float* bea0 = (const float*)d_in[13];
    const float* Wa1 = (const float*)d_in[14];
    const float* ba1 = (const float*)d_in[15];
    const float* ga1 = (const float*)d_in[16];
    const float* bea1 = (const float*)d_in[17];
    const float* Wa2 = (const float*)d_in[18];
    const float* ba2 = (const float*)d_in[19];
    const float* Wh0 = (const float*)d_in[20];
    const float* bh0 = (const float*)d_in[21];
    const float* Wh1 = (const float*)d_in[22];
    const float* bh1 = (const float*)d_in[23];
    const float* Wh2 = (const float*)d_in[24];
    const float* bh2 = (const float*)d_in[25];

    int N = in_sizes[0] / CH;
    int E = in_sizes[1] / 2;
    const int* esrc = eidx;
    const int* edst = eidx + E;

    __half* hw  = devptr_h(g_hw);
    float* actA  = devptr_f(g_actA);
    float* actB  = devptr_f(g_actB);
    float* dinv  = devptr_f(g_dinv);
    float* bnsum = devptr_f(g_bnsum);
    float* pool  = devptr_f(g_pool);
    float* y1    = devptr_f(g_y1);
    float* y2    = devptr_f(g_y2);
    int* indeg    = devptr_i(g_indeg);
    int* rowstart = devptr_i(g_rowstart);
    int* fill     = devptr_i(g_fill);
    int* edges    = devptr_i(g_edges);
    int* blocksum = devptr_i(g_blocksum);
    int* blockoff = devptr_i(g_blockoff);

    int gemmGrid = (N + BM - 1) / BM;
    int aggGrid  = (N + 7) / 8;
    int scanB = (N + 1023) / 1024;
    float invN = 1.0f / (float)N;

    // ---- CSR + degree prep ----
    k_init<<<128, 256>>>(indeg, bnsum, pool, N);
    k_count<<<(E + 255) / 256, 256>>>(edst, indeg, E);
    k_scan_blk<<<scanB, 1024>>>(indeg, rowstart, blocksum, dinv, N);
    k_scan_top<<<1, 32>>>(blocksum, blockoff, rowstart, scanB, N);
    k_scan_add<<<(N + 255) / 256, 256>>>(rowstart, blockoff, fill, N);

    // ---- Layer 0 GEMM (only needs dinv) ----
    k_gemm<<<gemmGrid, 256>>>(x, Wb0, dinv, nullptr, nullptr, nullptr, invN, hw, N);

    k_fillcsr<<<(E + 255) / 256, 256>>>(esrc, edst, fill, edges, E);

    // ---- Layer 0 agg (+ BN0 stats) ----
    k_agg<<<aggGrid, 256>>>(hw, edges, rowstart, dinv, bb0, actA, bnsum + 0 * 256,
                            nullptr, nullptr, nullptr, N);

    // ---- Layer 1: conv(gelu(BN0(actA))) -> actB ----
    k_gemm<<<gemmGrid, 256>>>(actA, Wb1, dinv, bnsum + 0 * 256, gb0, betab0, invN, hw, N);
    k_agg<<<aggGrid, 256>>>(hw, edges, rowstart, dinv, bb1, actB, nullptr,
                            nullptr, nullptr, nullptr, N);

    // ---- Layer 2: conv(actB) -> actA (+ BN1 stats) ----
    k_gemm<<<gemmGrid, 256>>>(actB, Wa0, dinv, nullptr, nullptr, nullptr, invN, hw, N);
    k_agg<<<aggGrid, 256>>>(hw, edges, rowstart, dinv, ba0, actA, bnsum + 1 * 256,
                            nullptr, nullptr, nullptr, N);

    // ---- Layer 3: conv(gelu(BN1(actA))) -> actB (+ BN2 stats) ----
    k_gemm<<<gemmGrid, 256>>>(actA, Wa1, dinv, bnsum + 1 * 256, ga0, bea0, invN, hw, N);
    k_agg<<<aggGrid, 256>>>(hw, edges, rowstart, dinv, ba1, actB, bnsum + 2 * 256,
                            nullptr, nullptr, nullptr, N);

    // ---- Layer 4: conv(gelu(BN2(actB))) -> fused mean-pool (no act store) ----
    k_gemm<<<gemmGrid, 256>>>(actB, Wa2, dinv, bnsum + 2 * 256, ga1, bea1, invN, hw, N);
    k_agg<<<aggGrid, 256>>>(hw, edges, rowstart, dinv, ba2, nullptr, nullptr,
                            batch, pool, pool + NGRAPHS * CH, N);

    // ---- head ----
    k_head1<<<NGRAPHS, CH>>>(pool, pool + NGRAPHS * CH, Wh0, bh0, y1);
    k_head2<<<NGRAPHS, CH>>>(y1, Wh1, bh1, y2);
    k_head3<<<NGRAPHS, CH>>>(y2, Wh2, bh2, (float*)d_out);
}

// round 17
// speedup vs baseline: 1.4535x; 1.0067x over previous
#include <cuda_runtime.h>
#include <cuda_fp16.h>
#include <math.h>

// ---------------- problem constants ----------------
#define NMAX      50000
#define EMAX      800000
#define CH        128
#define NGRAPHS   64
#define BN_EPS    1e-5f

// ---------------- scratch (device globals) ----------------
__device__ __half g_hw[NMAX * CH];    // GEMM output, rows pre-scaled by dinv (fp16)
__device__ float g_actA[NMAX * CH];
__device__ float g_actB[NMAX * CH];
__device__ float g_dinv[NMAX];
__device__ int   g_indeg[NMAX];
__device__ int   g_rowstart[NMAX + 1];
__device__ int   g_fill[NMAX];
__device__ int   g_edges[EMAX];
__device__ int   g_blocksum[64];
__device__ int   g_blockoff[64];
__device__ float g_bnsum[3 * 2 * CH];
__device__ float g_pool[NGRAPHS * CH + NGRAPHS];

// ---------------- helpers ----------------
__device__ __forceinline__ float gelu_exact(float x) {
    return 0.5f * x * (1.0f + erff(x * 0.70710678118654752440f));
}

// tanh-form gelu using HW MUFU.TANH (sm_90+)
__device__ __forceinline__ float gelu_fast(float x) {
    float u = x * (0.7978845608028654f + 0.035677408136300125f * x * x);
    float t;
    asm("tanh.approx.f32 %0, %1;" : "=f"(t) : "f"(u));
    return 0.5f * x * (1.0f + t);
}

__device__ __forceinline__ unsigned h2u(__half2 h) { return *reinterpret_cast<unsigned*>(&h); }

__device__ __forceinline__ void ldsm_x4(unsigned r[4], const void* p) {
    unsigned addr = (unsigned)__cvta_generic_to_shared(p);
    asm volatile("ldmatrix.sync.aligned.m8n8.x4.shared.b16 {%0,%1,%2,%3}, [%4];"
                 : "=r"(r[0]), "=r"(r[1]), "=r"(r[2]), "=r"(r[3]) : "r"(addr));
}
__device__ __forceinline__ void ldsm_x4_t(unsigned r[4], const void* p) {
    unsigned addr = (unsigned)__cvta_generic_to_shared(p);
    asm volatile("ldmatrix.sync.aligned.m8n8.x4.trans.shared.b16 {%0,%1,%2,%3}, [%4];"
                 : "=r"(r[0]), "=r"(r[1]), "=r"(r[2]), "=r"(r[3]) : "r"(addr));
}
__device__ __forceinline__ void mma16816(float c[4], const unsigned a[4],
                                         unsigned b0, unsigned b1) {
    asm volatile(
        "mma.sync.aligned.m16n8k16.row.col.f32.f16.f16.f32 "
        "{%0,%1,%2,%3}, {%4,%5,%6,%7}, {%8,%9}, {%0,%1,%2,%3};"
        : "+f"(c[0]), "+f"(c[1]), "+f"(c[2]), "+f"(c[3])
        : "r"(a[0]), "r"(a[1]), "r"(a[2]), "r"(a[3]), "r"(b0), "r"(b1));
}

// ---------------- init ----------------
__global__ void k_init(int* __restrict__ indeg, float* __restrict__ bnsum,
                       float* __restrict__ pool, int N) {
    int i = blockIdx.x * blockDim.x + threadIdx.x;
    int st = gridDim.x * blockDim.x;
    for (int j = i; j < N; j += st) indeg[j] = 0;
    for (int j = i; j < 3 * 2 * CH; j += st) bnsum[j] = 0.f;
    for (int j = i; j < NGRAPHS * CH + NGRAPHS; j += st) pool[j] = 0.f;
}

// ---------------- degree / CSR build ----------------
__global__ void k_count(const int* __restrict__ dst, int* __restrict__ indeg, int E) {
    int i = blockIdx.x * blockDim.x + threadIdx.x;
    if (i < E) atomicAdd(&indeg[dst[i]], 1);
}

__global__ void k_scan_blk(const int* __restrict__ indeg, int* __restrict__ scanned,
                           int* __restrict__ blocksum, float* __restrict__ dinv, int N) {
    __shared__ int wsum[32];
    int tid = threadIdx.x, lane = tid & 31, wid = tid >> 5;
    int idx = blockIdx.x * 1024 + tid;
    int v = (idx < N) ? indeg[idx] : 0;
    if (idx < N) dinv[idx] = rsqrtf((float)(v + 1));
    int x = v;
    #pragma unroll
    for (int off = 1; off < 32; off <<= 1) {
        int y = __shfl_up_sync(0xffffffffu, x, off);
        if (lane >= off) x += y;
    }
    if (lane == 31) wsum[wid] = x;
    __syncthreads();
    if (wid == 0) {
        int w = wsum[lane];
        #pragma unroll
        for (int off = 1; off < 32; off <<= 1) {
            int y = __shfl_up_sync(0xffffffffu, w, off);
            if (lane >= off) w += y;
        }
        wsum[lane] = w;
    }
    __syncthreads();
    int excl = x - v + (wid ? wsum[wid - 1] : 0);
    if (idx < N) scanned[idx] = excl;
    if (tid == 1023) blocksum[blockIdx.x] = excl + v;
}

__global__ void k_scan_top(const int* __restrict__ blocksum, int* __restrict__ blockoff,
                           int* __restrict__ rowstart, int B, int N) {
    int lane = threadIdx.x;
    int run = 0;
    for (int base = 0; base < B; base += 32) {
        int v = (base + lane < B) ? blocksum[base + lane] : 0;
        int x = v;
        #pragma unroll
        for (int off = 1; off < 32; off <<= 1) {
            int y = __shfl_up_sync(0xffffffffu, x, off);
            if (lane >= off) x += y;
        }
        if (base + lane < B) blockoff[base + lane] = x - v + run;
        run += __shfl_sync(0xffffffffu, x, 31);
    }
    if (lane == 0) rowstart[N] = run;
}

__global__ void k_scan_add(int* __restrict__ rowstart, const int* __restrict__ blockoff,
                           int* __restrict__ fill, int N) {
    int idx = blockIdx.x * blockDim.x + threadIdx.x;
    if (idx < N) {
        int v = rowstart[idx] + blockoff[idx >> 10];
        rowstart[idx] = v;
        fill[idx] = v;
    }
}

__global__ void k_fillcsr(const int* __restrict__ src, const int* __restrict__ dst,
                          int* __restrict__ fill, int* __restrict__ edges, int E) {
    int i = blockIdx.x * blockDim.x + threadIdx.x;
    if (i < E) {
        int pos = atomicAdd(&fill[dst[i]], 1);
        edges[pos] = src[i];
    }
}

// ---------------- tensor-core GEMM with optional fused BN+gelu on A ----------------
// out[r] = (half) dinv[r] * ( f(A[r]) @ W ),  f = gelu(A*scl+shf) if bnsum else identity
#define BM 128

__global__ void __launch_bounds__(256, 2)
k_gemm(const float* __restrict__ A, const float* __restrict__ W,
       const float* __restrict__ dinv,
       const float* __restrict__ bnsum, const float* __restrict__ gamma,
       const float* __restrict__ beta, float invN,
       __half* __restrict__ out, int N) {
    __shared__ __half sA[128][72];
    __shared__ __half sB[64][136];
    __shared__ float scl[CH], shf[CH];

    int tid = threadIdx.x;
    int lane = tid & 31, wid = tid >> 5;
    int warpM = wid >> 1, warpN = wid & 1;
    int rowBase = blockIdx.x * BM;

    if (bnsum) {
        if (tid < CH) {
            float mean = bnsum[tid] * invN;
            float var = bnsum[CH + tid] * invN - mean * mean;
            float s = gamma[tid] * rsqrtf(var + BN_EPS);
            scl[tid] = s;
            shf[tid] = beta[tid] - mean * s;
        }
        __syncthreads();
    }

    float acc[2][8][4];
    #pragma unroll
    for (int mi = 0; mi < 2; mi++)
        #pragma unroll
        for (int ni = 0; ni < 8; ni++)
            #pragma unroll
            for (int j = 0; j < 4; j++) acc[mi][ni][j] = 0.f;

    for (int kt = 0; kt < CH; kt += 64) {
        #pragma unroll
        for (int i = 0; i < 8; i++) {
            int p = tid + i * 256;
            int r = p >> 4, c4 = p & 15;
            float4 v = make_float4(0.f, 0.f, 0.f, 0.f);
            int grow = rowBase + r;
            if (grow < N) v = *(const float4*)&A[grow * CH + kt + c4 * 4];
            if (bnsum) {
                int c = kt + c4 * 4;
                v.x = gelu_fast(v.x * scl[c + 0] + shf[c + 0]);
                v.y = gelu_fast(v.y * scl[c + 1] + shf[c + 1]);
                v.z = gelu_fast(v.z * scl[c + 2] + shf[c + 2]);
                v.w = gelu_fast(v.w * scl[c + 3] + shf[c + 3]);
            }
            __half2 h0 = __floats2half2_rn(v.x, v.y);
            __half2 h1 = __floats2half2_rn(v.z, v.w);
            *(uint2*)&sA[r][c4 * 4] = make_uint2(h2u(h0), h2u(h1));
        }
        #pragma unroll
        for (int i = 0; i < 8; i++) {
            int p = tid + i * 256;
            int r = p >> 5, c4 = p & 31;
            float4 v = *(const float4*)&W[(kt + r) * CH + c4 * 4];
            __half2 h0 = __floats2half2_rn(v.x, v.y);
            __half2 h1 = __floats2half2_rn(v.z, v.w);
            *(uint2*)&sB[r][c4 * 4] = make_uint2(h2u(h0), h2u(h1));
        }
        __syncthreads();

        #pragma unroll
        for (int ks = 0; ks < 64; ks += 16) {
            unsigned af[2][4];
            #pragma unroll
            for (int mi = 0; mi < 2; mi++) {
                int r = warpM * 32 + mi * 16 + (lane & 15);
                int c = ks + (lane >> 4) * 8;
                ldsm_x4(af[mi], &sA[r][c]);
            }
            unsigned bf[4][4];
            #pragma unroll
            for (int nj = 0; nj < 4; nj++) {
                int r = ks + (lane & 15);
                int c = warpN * 64 + nj * 16 + (lane >> 4) * 8;
                ldsm_x4_t(bf[nj], &sB[r][c]);
            }
            #pragma unroll
            for (int mi = 0; mi < 2; mi++)
                #pragma unroll
                for (int ni = 0; ni < 8; ni++)
                    mma16816(acc[mi][ni], af[mi],
                             bf[ni >> 1][(ni & 1) * 2], bf[ni >> 1][(ni & 1) * 2 + 1]);
        }
        __syncthreads();
    }

    #pragma unroll
    for (int mi = 0; mi < 2; mi++) {
        int r0 = rowBase + warpM * 32 + mi * 16 + (lane >> 2);
        int r1 = r0 + 8;
        float d0 = (r0 < N) ? dinv[r0] : 0.f;
        float d1 = (r1 < N) ? dinv[r1] : 0.f;
        #pragma unroll
        for (int ni = 0; ni < 8; ni++) {
            int col = warpN * 64 + ni * 8 + (lane & 3) * 2;
            if (r0 < N) {
                __half2 h = __floats2half2_rn(acc[mi][ni][0] * d0, acc[mi][ni][1] * d0);
                *(__half2*)&out[r0 * CH + col] = h;
            }
            if (r1 < N) {
                __half2 h = __floats2half2_rn(acc[mi][ni][2] * d1, acc[mi][ni][3] * d1);
                *(__half2*)&out[r1 * CH + col] = h;
            }
        }
    }
}

// ---------------- aggregation (fp16 gather, MLP-8 batches) ----------------
// optional fused BN stats (stats != null) OR fused mean-pool (psum != null)
__device__ __forceinline__ void acc_h4(float4& a, uint2 v) {
    __half2 h0 = *reinterpret_cast<__half2*>(&v.x);
    __half2 h1 = *reinterpret_cast<__half2*>(&v.y);
    float2 f0 = __half22float2(h0);
    float2 f1 = __half22float2(h1);
    a.x += f0.x; a.y += f0.y; a.z += f1.x; a.w += f1.y;
}

__global__ void k_agg(const __half* __restrict__ hws, const int* __restrict__ edges,
                      const int* __restrict__ rowstart, const float* __restrict__ dinv,
                      const float* __restrict__ bias, float* __restrict__ outf,
                      float* __restrict__ stats,
                      const int* __restrict__ batch, float* __restrict__ psum,
                      float* __restrict__ pcnt, int N) {
    __shared__ float sh[8][CH];
    __shared__ int gid[8];
    int wId = threadIdx.x >> 5;
    int lane = threadIdx.x & 31;
    int node = blockIdx.x * 8 + wId;
    bool valid = node < N;

    const uint2* base = (const uint2*)hws;
    float4 acc = make_float4(0.f, 0.f, 0.f, 0.f);
    float4 acc2 = make_float4(0.f, 0.f, 0.f, 0.f);
    int s = 0, e = 0;
    float d = 0.f;
    if (valid) {
        acc_h4(acc, base[node * 32 + lane]);   // self loop (pre-scaled by dinv)
        s = rowstart[node]; e = rowstart[node + 1];
        d = dinv[node];
    }
    int i = s;
    for (; i + 7 < e; i += 8) {
        int idx[8];
        #pragma unroll
        for (int j = 0; j < 8; j++) idx[j] = __ldg(&edges[i + j]);
        uint2 v[8];
        #pragma unroll
        for (int j = 0; j < 8; j++) v[j] = base[idx[j] * 32 + lane];
        #pragma unroll
        for (int j = 0; j < 8; j += 2) { acc_h4(acc, v[j]); acc_h4(acc2, v[j + 1]); }
    }
    for (; i + 1 < e; i += 2) {
        int i0 = __ldg(&edges[i]);
        int i1 = __ldg(&edges[i + 1]);
        uint2 v0 = base[i0 * 32 + lane];
        uint2 v1 = base[i1 * 32 + lane];
        acc_h4(acc, v0); acc_h4(acc2, v1);
    }
    if (i < e) acc_h4(acc, base[__ldg(&edges[i]) * 32 + lane]);
    acc.x += acc2.x; acc.y += acc2.y; acc.z += acc2.z; acc.w += acc2.w;

    float4 o = make_float4(0.f, 0.f, 0.f, 0.f);
    if (valid) {
        float4 bb = ((const float4*)bias)[lane];
        o.x = acc.x * d + bb.x; o.y = acc.y * d + bb.y;
        o.z = acc.z * d + bb.z; o.w = acc.w * d + bb.w;
        if (outf) ((float4*)outf)[node * 32 + lane] = o;
    }
    if (stats) {
        *(float4*)&sh[wId][lane * 4] = o;
        __syncthreads();
        int t = threadIdx.x;
        int c = t & 127;
        bool sq = t >= 128;
        float a2 = 0.f;
        #pragma unroll
        for (int w = 0; w < 8; w++) {
            float v = sh[w][c];
            a2 += sq ? v * v : v;
        }
        atomicAdd(&stats[sq ? CH + c : c], a2);
    }
    if (psum) {
        *(float4*)&sh[wId][lane * 4] = o;     // zeros for invalid nodes
        if (lane == 0) gid[wId] = valid ? __ldg(&batch[node]) : -1;
        __syncthreads();
        int t = threadIdx.x;
        if (t < 128) {
            // batch is sorted: nodes in this block span 1-2 graphs; run-length flush
            float a2 = 0.f;
            int cur = -2;
            #pragma unroll
            for (int w = 0; w < 8; w++) {
                int g = gid[w];
                if (g != cur) {
                    if (cur >= 0) atomicAdd(&psum[cur * CH + t], a2);
                    cur = g; a2 = 0.f;
                }
                a2 += sh[w][t];
            }
            if (cur >= 0) atomicAdd(&psum[cur * CH + t], a2);
        } else if (t == 128) {
            float c = 0.f;
            int cur = -2;
            #pragma unroll
            for (int w = 0; w < 8; w++) {
                int g = gid[w];
                if (g != cur) {
                    if (cur >= 0) atomicAdd(&pcnt[cur], c);
                    cur = g; c = 0.f;
                }
                if (g >= 0) c += 1.f;
            }
            if (cur >= 0) atomicAdd(&pcnt[cur], c);
        }
    }
}

// ---------------- fused 3-layer MLP head: one block per graph ----------------
__global__ void k_head(const float* __restrict__ psum, const float* __restrict__ pcnt,
                       const float* __restrict__ Wh0, const float* __restrict__ bh0,
                       const float* __restrict__ Wh1, const float* __restrict__ bh1,
                       const float* __restrict__ Wh2, const float* __restrict__ bh2,
                       float* __restrict__ out) {
    __shared__ float rowA[CH];
    __shared__ float rowB[CH];
    int g = blockIdx.x, t = threadIdx.x;
    float cnt = fmaxf(pcnt[g], 1.0f);
    rowA[t] = psum[g * CH + t] / cnt;
    __syncthreads();
    // layer 1
    float acc = bh0[t];
    #pragma unroll 8
    for (int k = 0; k < CH; k++) acc += rowA[k] * Wh0[k * CH + t];
    rowB[t] = gelu_exact(acc);
    __syncthreads();
    // layer 2
    acc = bh1[t];
    #pragma unroll 8
    for (int k = 0; k < CH; k++) acc += rowB[k] * Wh1[k * CH + t];
    rowA[t] = gelu_exact(acc);
    __syncthreads();
    // layer 3 (10 outputs)
    if (t < 10) {
        acc = bh2[t];
        #pragma unroll 8
        for (int k = 0; k < CH; k++) acc += rowA[k] * Wh2[k * 10 + t];
        out[g * 10 + t] = acc;
    }
}

// ---------------- driver ----------------
static float* devptr_f(const void* sym) { void* p = nullptr; cudaGetSymbolAddress(&p, sym); return (float*)p; }
static int* devptr_i(const void* sym) { void* p = nullptr; cudaGetSymbolAddress(&p, sym); return (int*)p; }
static __half* devptr_h(const void* sym) { void* p = nullptr; cudaGetSymbolAddress(&p, sym); return (__half*)p; }

extern "C" void kernel_launch(void* const* d_in, const int* in_sizes, int n_in,
                              void* d_out, int out_size) {
    const float* x      = (const float*)d_in[0];
    const int*   eidx   = (const int*)d_in[1];
    const int*   batch  = (const int*)d_in[2];
    const float* Wb0 = (const float*)d_in[4];
    const float* bb0 = (const float*)d_in[5];
    const float* gb0 = (const float*)d_in[6];
    const float* betab0 = (const float*)d_in[7];
    const float* Wb1 = (const float*)d_in[8];
    const float* bb1 = (const float*)d_in[9];
    const float* Wa0 = (const float*)d_in[10];
    const float* ba0 = (const float*)d_in[11];
    const float* ga0 = (const float*)d_in[12];
    const float* bea0 = (const float*)d_in[13];
    const float* Wa1 = (const float*)d_in[14];
    const float* ba1 = (const float*)d_in[15];
    const float* ga1 = (const float*)d_in[16];
    const float* bea1 = (const float*)d_in[17];
    const float* Wa2 = (const float*)d_in[18];
    const float* ba2 = (const float*)d_in[19];
    const float* Wh0 = (const float*)d_in[20];
    const float* bh0 = (const float*)d_in[21];
    const float* Wh1 = (const float*)d_in[22];
    const float* bh1 = (const float*)d_in[23];
    const float* Wh2 = (const float*)d_in[24];
    const float* bh2 = (const float*)d_in[25];

    int N = in_sizes[0] / CH;
    int E = in_sizes[1] / 2;
    const int* esrc = eidx;
    const int* edst = eidx + E;

    __half* hw  = devptr_h(g_hw);
    float* actA  = devptr_f(g_actA);
    float* actB  = devptr_f(g_actB);
    float* dinv  = devptr_f(g_dinv);
    float* bnsum = devptr_f(g_bnsum);
    float* pool  = devptr_f(g_pool);
    int* indeg    = devptr_i(g_indeg);
    int* rowstart = devptr_i(g_rowstart);
    int* fill     = devptr_i(g_fill);
    int* edges    = devptr_i(g_edges);
    int* blocksum = devptr_i(g_blocksum);
    int* blockoff = devptr_i(g_blockoff);

    int gemmGrid = (N + BM - 1) / BM;
    int aggGrid  = (N + 7) / 8;
    int scanB = (N + 1023) / 1024;
    float invN = 1.0f / (float)N;

    // ---- CSR + degree prep (GEMM L0 moved to 4th slot for ncu visibility) ----
    k_init<<<128, 256>>>(indeg, bnsum, pool, N);
    k_count<<<(E + 255) / 256, 256>>>(edst, indeg, E);
    k_scan_blk<<<scanB, 1024>>>(indeg, rowstart, blocksum, dinv, N);

    // ---- Layer 0 GEMM (only needs dinv) — 4th launch, gets profiled ----
    k_gemm<<<gemmGrid, 256>>>(x, Wb0, dinv, nullptr, nullptr, nullptr, invN, hw, N);

    k_scan_top<<<1, 32>>>(blocksum, blockoff, rowstart, scanB, N);
    k_scan_add<<<(N + 255) / 256, 256>>>(rowstart, blockoff, fill, N);
    k_fillcsr<<<(E + 255) / 256, 256>>>(esrc, edst, fill, edges, E);

    // ---- Layer 0 agg (+ BN0 stats) ----
    k_agg<<<aggGrid, 256>>>(hw, edges, rowstart, dinv, bb0, actA, bnsum + 0 * 256,
                            nullptr, nullptr, nullptr, N);

    // ---- Layer 1: conv(gelu(BN0(actA))) -> actB ----
    k_gemm<<<gemmGrid, 256>>>(actA, Wb1, dinv, bnsum + 0 * 256, gb0, betab0, invN, hw, N);
    k_agg<<<aggGrid, 256>>>(hw, edges, rowstart, dinv, bb1, actB, nullptr,
                            nullptr, nullptr, nullptr, N);

    // ---- Layer 2: conv(actB) -> actA (+ BN1 stats) ----
    k_gemm<<<gemmGrid, 256>>>(actB, Wa0, dinv, nullptr, nullptr, nullptr, invN, hw, N);
    k_agg<<<aggGrid, 256>>>(hw, edges, rowstart, dinv, ba0, actA, bnsum + 1 * 256,
                            nullptr, nullptr, nullptr, N);

    // ---- Layer 3: conv(gelu(BN1(actA))) -> actB (+ BN2 stats) ----
    k_gemm<<<gemmGrid, 256>>>(actA, Wa1, dinv, bnsum + 1 * 256, ga0, bea0, invN, hw, N);
    k_agg<<<aggGrid, 256>>>(hw, edges, rowstart, dinv, ba1, actB, bnsum + 2 * 256,
                            nullptr, nullptr, nullptr, N);

    // ---- Layer 4: conv(gelu(BN2(actB))) -> fused mean-pool (no act store) ----
    k_gemm<<<gemmGrid, 256>>>(actB, Wa2, dinv, bnsum + 2 * 256, ga1, bea1, invN, hw, N);
    k_agg<<<aggGrid, 256>>>(hw, edges, rowstart, dinv, ba2, nullptr, nullptr,
                            batch, pool, pool + NGRAPHS * CH, N);

    // ---- fused 3-layer head ----
    k_head<<<NGRAPHS, CH>>>(pool, pool + NGRAPHS * CH, Wh0, bh0, Wh1, bh1, Wh2, bh2,
                            (float*)d_out);
}